// round 1
// baseline (speedup 1.0000x reference)
#include <cuda_runtime.h>
#include <cstdint>

#define BATCH 16
#define SEQ   1024
#define CH    768
#define HEADS 12
#define DHEAD 64
#define NTOK  1220              // 1024 + 196
#define NKV   1280              // padded key count
#define MQKV  (BATCH*NTOK)      // 19520 rows of xt
#define QKVN  (3*CH)            // 2304

// ---------------- scratch (zero-initialized at module load; pad rows of K/V
// are never written so they stay 0.0 deterministically across graph replays) --
__device__ float g_Q [BATCH*HEADS*SEQ *DHEAD];   // [b][h][t<1024][d]
__device__ float g_K [BATCH*HEADS*NKV *DHEAD];   // [b][h][t<1280][d]
__device__ float g_V [BATCH*HEADS*NKV *DHEAD];
__device__ float g_AT[BATCH*SEQ*CH];             // attention out, [b*1024+t][h*64+d]

// ---------------- tf32 helpers ----------------
__device__ __forceinline__ unsigned f2t(float x){
    unsigned u; asm("cvt.rna.tf32.f32 %0, %1;" : "=r"(u) : "f"(x)); return u;
}
__device__ __forceinline__ void mma8(float* c, const unsigned* a, const unsigned* b){
    asm volatile("mma.sync.aligned.m16n8k8.row.col.f32.tf32.tf32.f32 "
        "{%0,%1,%2,%3}, {%4,%5,%6,%7}, {%8,%9}, {%0,%1,%2,%3};"
        : "+f"(c[0]), "+f"(c[1]), "+f"(c[2]), "+f"(c[3])
        : "r"(a[0]), "r"(a[1]), "r"(a[2]), "r"(a[3]), "r"(b[0]), "r"(b[1]));
}

// =====================================================================
// Kernel 1: QKV GEMM.  xt[19520,768] @ W_qkv[768,2304], scatter into
// g_Q/g_K/g_V head-major layouts.  Block tile 128x128, k-tile 32,
// 8 warps (4 m x 2 n), warp tile 32x64.
// =====================================================================
__global__ __launch_bounds__(256) void qkv_gemm(
    const float* __restrict__ x, const float* __restrict__ sc,
    const float* __restrict__ W)
{
    __shared__ unsigned As[128][36];   // [m][k], pad 36 -> conflict-free frag loads
    __shared__ unsigned Bs[32][132];   // [k][n]

    const int mt = blockIdx.y, nt = blockIdx.x;
    const int tid = threadIdx.x;
    const int wid = tid >> 5, lane = tid & 31;
    const int g = lane >> 2, tg = lane & 3;
    const int wm = (wid & 3) * 32, wn = (wid >> 2) * 64;

    float Creg[2][8][4];
    #pragma unroll
    for (int i = 0; i < 2; i++)
        #pragma unroll
        for (int j = 0; j < 8; j++)
            #pragma unroll
            for (int e = 0; e < 4; e++) Creg[i][j][e] = 0.f;

    for (int kt = 0; kt < CH / 32; kt++) {
        const int kt0 = kt * 32;
        // ---- load A tile (with xt row mapping) ----
        #pragma unroll
        for (int i = 0; i < 4; i++) {
            int slot = tid + i * 256;
            int row = slot >> 3, kc = (slot & 7) * 4;
            int gr = mt * 128 + row;
            float4 v = make_float4(0.f, 0.f, 0.f, 0.f);
            if (gr < MQKV) {
                int b = gr / NTOK, t = gr - b * NTOK;
                const float* src = (t < SEQ) ? (x + (size_t)(b * SEQ + t) * CH)
                                             : (sc + (size_t)(t - SEQ) * CH);
                v = *(const float4*)(src + kt0 + kc);
            }
            *(uint4*)&As[row][kc] = make_uint4(f2t(v.x), f2t(v.y), f2t(v.z), f2t(v.w));
        }
        // ---- load B tile ----
        #pragma unroll
        for (int i = 0; i < 4; i++) {
            int slot = tid + i * 256;
            int kr = slot >> 5, nc = (slot & 31) * 4;
            float4 v = *(const float4*)(W + (size_t)(kt0 + kr) * QKVN + nt * 128 + nc);
            *(uint4*)&Bs[kr][nc] = make_uint4(f2t(v.x), f2t(v.y), f2t(v.z), f2t(v.w));
        }
        __syncthreads();
        // ---- compute ----
        #pragma unroll
        for (int ks = 0; ks < 4; ks++) {
            const int kk = ks * 8;
            unsigned a[2][4];
            #pragma unroll
            for (int mf = 0; mf < 2; mf++) {
                int r0 = wm + mf * 16 + g;
                a[mf][0] = As[r0    ][kk + tg];
                a[mf][1] = As[r0 + 8][kk + tg];
                a[mf][2] = As[r0    ][kk + tg + 4];
                a[mf][3] = As[r0 + 8][kk + tg + 4];
            }
            unsigned bf[8][2];
            #pragma unroll
            for (int nf = 0; nf < 8; nf++) {
                int c0 = wn + nf * 8 + g;
                bf[nf][0] = Bs[kk + tg    ][c0];
                bf[nf][1] = Bs[kk + tg + 4][c0];
            }
            #pragma unroll
            for (int mf = 0; mf < 2; mf++)
                #pragma unroll
                for (int nf = 0; nf < 8; nf++)
                    mma8(Creg[mf][nf], a[mf], bf[nf]);
        }
        __syncthreads();
    }
    // ---- epilogue: scatter into Q/K/V ----
    #pragma unroll
    for (int mf = 0; mf < 2; mf++) {
        #pragma unroll
        for (int nf = 0; nf < 8; nf++) {
            #pragma unroll
            for (int e = 0; e < 4; e++) {
                int r = mt * 128 + wm + mf * 16 + g + ((e >= 2) ? 8 : 0);
                int c = nt * 128 + wn + nf * 8 + tg * 2 + (e & 1);
                if (r >= MQKV) continue;
                int b = r / NTOK, t = r - b * NTOK;
                int which = c / CH, cc = c - which * CH;
                int h = cc >> 6, d = cc & 63;
                float v = Creg[mf][nf][e];
                if (which == 0) {
                    if (t < SEQ) g_Q[((size_t)(b * HEADS + h) * SEQ + t) * DHEAD + d] = v;
                } else if (which == 1) {
                    g_K[((size_t)(b * HEADS + h) * NKV + t) * DHEAD + d] = v;
                } else {
                    g_V[((size_t)(b * HEADS + h) * NKV + t) * DHEAD + d] = v;
                }
            }
        }
    }
}

// =====================================================================
// Kernel 2: flash attention.  grid = (16 q-tiles, 192 bh), 4 warps.
// Each block: 64 q rows; loop 20 kv tiles of 64 keys (mask j>=1220).
// Q frags held in registers; P routed through the K smem buffer.
// =====================================================================
__global__ __launch_bounds__(128) void attn_kernel()
{
    __shared__ unsigned Ks[64][72];   // K tile, then reused for P
    __shared__ unsigned Vs[64][72];

    const int bh = blockIdx.y, qt = blockIdx.x;
    const int b = bh / HEADS, h = bh - b * HEADS;
    const int tid = threadIdx.x;
    const int w = tid >> 5, lane = tid & 31;
    const int g = lane >> 2, tg = lane & 3;

    const float* Qp = g_Q + (size_t)bh * SEQ * DHEAD;
    const float* Kp = g_K + (size_t)bh * NKV * DHEAD;
    const float* Vp = g_V + (size_t)bh * NKV * DHEAD;
    const int q0 = qt * 64 + w * 16;

    // Q fragments (row-major A, k = d)
    unsigned aq[8][4];
    #pragma unroll
    for (int ks = 0; ks < 8; ks++) {
        aq[ks][0] = f2t(Qp[(size_t)(q0 + g    ) * DHEAD + ks * 8 + tg    ]);
        aq[ks][1] = f2t(Qp[(size_t)(q0 + g + 8) * DHEAD + ks * 8 + tg    ]);
        aq[ks][2] = f2t(Qp[(size_t)(q0 + g    ) * DHEAD + ks * 8 + tg + 4]);
        aq[ks][3] = f2t(Qp[(size_t)(q0 + g + 8) * DHEAD + ks * 8 + tg + 4]);
    }

    float O[8][4];
    #pragma unroll
    for (int i = 0; i < 8; i++)
        #pragma unroll
        for (int e = 0; e < 4; e++) O[i][e] = 0.f;
    float mrow[2] = { -1e30f, -1e30f };
    float lrow[2] = { 0.f, 0.f };

    for (int kt = 0; kt < NKV / 64; kt++) {
        const int j0 = kt * 64;
        // ---- load K,V tiles (pad rows are zero-init, never written) ----
        #pragma unroll
        for (int i = 0; i < 8; i++) {
            int slot = tid + i * 128;
            int row = slot >> 4, c4 = (slot & 15) * 4;
            float4 kv = *(const float4*)(Kp + (size_t)(j0 + row) * DHEAD + c4);
            *(uint4*)&Ks[row][c4] = make_uint4(f2t(kv.x), f2t(kv.y), f2t(kv.z), f2t(kv.w));
            float4 vv = *(const float4*)(Vp + (size_t)(j0 + row) * DHEAD + c4);
            *(uint4*)&Vs[row][c4] = make_uint4(f2t(vv.x), f2t(vv.y), f2t(vv.z), f2t(vv.w));
        }
        __syncthreads();

        // ---- scores S = Q @ K^T  (B[k=d][n=key] = Ks[key][d]) ----
        float S[8][4];
        #pragma unroll
        for (int i = 0; i < 8; i++)
            #pragma unroll
            for (int e = 0; e < 4; e++) S[i][e] = 0.f;
        #pragma unroll
        for (int nf = 0; nf < 8; nf++) {
            #pragma unroll
            for (int ks = 0; ks < 8; ks++) {
                unsigned bb[2];
                bb[0] = Ks[nf * 8 + g][ks * 8 + tg    ];
                bb[1] = Ks[nf * 8 + g][ks * 8 + tg + 4];
                mma8(S[nf], aq[ks], bb);
            }
        }
        __syncthreads();   // everyone done reading Ks before it becomes P

        // ---- scale + mask ----
        #pragma unroll
        for (int nf = 0; nf < 8; nf++) {
            #pragma unroll
            for (int e = 0; e < 4; e++) {
                float s = S[nf][e] * 0.125f;
                int j = j0 + nf * 8 + tg * 2 + (e & 1);
                if (j >= NTOK) s = -1e30f;
                S[nf][e] = s;
            }
        }
        // ---- online softmax (thread owns rows g and g+8 of the warp tile) ----
        #pragma unroll
        for (int r = 0; r < 2; r++) {
            float mx = -1e30f;
            #pragma unroll
            for (int nf = 0; nf < 8; nf++) {
                mx = fmaxf(mx, S[nf][2 * r]);
                mx = fmaxf(mx, S[nf][2 * r + 1]);
            }
            mx = fmaxf(mx, __shfl_xor_sync(0xffffffffu, mx, 1));
            mx = fmaxf(mx, __shfl_xor_sync(0xffffffffu, mx, 2));
            float mnew = fmaxf(mrow[r], mx);
            float alpha = __expf(mrow[r] - mnew);
            float sum = 0.f;
            #pragma unroll
            for (int nf = 0; nf < 8; nf++) {
                float p0 = __expf(S[nf][2 * r    ] - mnew);
                float p1 = __expf(S[nf][2 * r + 1] - mnew);
                S[nf][2 * r] = p0; S[nf][2 * r + 1] = p1;
                sum += p0 + p1;
            }
            sum += __shfl_xor_sync(0xffffffffu, sum, 1);
            sum += __shfl_xor_sync(0xffffffffu, sum, 2);
            lrow[r] = lrow[r] * alpha + sum;
            mrow[r] = mnew;
            #pragma unroll
            for (int nf = 0; nf < 8; nf++) {
                O[nf][2 * r] *= alpha; O[nf][2 * r + 1] *= alpha;
            }
        }
        // ---- store P into Ks (warp-private 16 rows) ----
        #pragma unroll
        for (int nf = 0; nf < 8; nf++) {
            Ks[w * 16 + g    ][nf * 8 + tg * 2    ] = f2t(S[nf][0]);
            Ks[w * 16 + g    ][nf * 8 + tg * 2 + 1] = f2t(S[nf][1]);
            Ks[w * 16 + g + 8][nf * 8 + tg * 2    ] = f2t(S[nf][2]);
            Ks[w * 16 + g + 8][nf * 8 + tg * 2 + 1] = f2t(S[nf][3]);
        }
        __syncwarp();
        // ---- O += P @ V   (A = P 16x64, B[k=key][n=d] = Vs[key][d]) ----
        #pragma unroll
        for (int ks = 0; ks < 8; ks++) {
            unsigned ap[4];
            ap[0] = Ks[w * 16 + g    ][ks * 8 + tg    ];
            ap[1] = Ks[w * 16 + g + 8][ks * 8 + tg    ];
            ap[2] = Ks[w * 16 + g    ][ks * 8 + tg + 4];
            ap[3] = Ks[w * 16 + g + 8][ks * 8 + tg + 4];
            #pragma unroll
            for (int nf = 0; nf < 8; nf++) {
                unsigned bb[2];
                bb[0] = Vs[ks * 8 + tg    ][nf * 8 + g];
                bb[1] = Vs[ks * 8 + tg + 4][nf * 8 + g];
                mma8(O[nf], ap, bb);
            }
        }
        __syncthreads();   // before next tile overwrites Ks/Vs
    }
    // ---- normalize and write to g_AT [b*1024+t][h*64+d] ----
    float inv0 = 1.f / lrow[0], inv1 = 1.f / lrow[1];
    int row0 = b * SEQ + qt * 64 + w * 16 + g;
    #pragma unroll
    for (int nf = 0; nf < 8; nf++) {
        int col = h * DHEAD + nf * 8 + tg * 2;
        g_AT[(size_t)row0 * CH + col    ] = O[nf][0] * inv0;
        g_AT[(size_t)row0 * CH + col + 1] = O[nf][1] * inv0;
        g_AT[(size_t)(row0 + 8) * CH + col    ] = O[nf][2] * inv1;
        g_AT[(size_t)(row0 + 8) * CH + col + 1] = O[nf][3] * inv1;
    }
}

// =====================================================================
// Kernel 3: proj GEMM + bias.  g_AT[16384,768] @ W_proj[768,768] + b.
// =====================================================================
__global__ __launch_bounds__(256) void proj_gemm(
    const float* __restrict__ W, const float* __restrict__ bias,
    float* __restrict__ out)
{
    __shared__ unsigned As[128][36];
    __shared__ unsigned Bs[32][132];

    const int mt = blockIdx.y, nt = blockIdx.x;
    const int tid = threadIdx.x;
    const int wid = tid >> 5, lane = tid & 31;
    const int g = lane >> 2, tg = lane & 3;
    const int wm = (wid & 3) * 32, wn = (wid >> 2) * 64;

    float Creg[2][8][4];
    #pragma unroll
    for (int i = 0; i < 2; i++)
        #pragma unroll
        for (int j = 0; j < 8; j++)
            #pragma unroll
            for (int e = 0; e < 4; e++) Creg[i][j][e] = 0.f;

    for (int kt = 0; kt < CH / 32; kt++) {
        const int kt0 = kt * 32;
        #pragma unroll
        for (int i = 0; i < 4; i++) {
            int slot = tid + i * 256;
            int row = slot >> 3, kc = (slot & 7) * 4;
            float4 v = *(const float4*)(g_AT + (size_t)(mt * 128 + row) * CH + kt0 + kc);
            *(uint4*)&As[row][kc] = make_uint4(f2t(v.x), f2t(v.y), f2t(v.z), f2t(v.w));
        }
        #pragma unroll
        for (int i = 0; i < 4; i++) {
            int slot = tid + i * 256;
            int kr = slot >> 5, nc = (slot & 31) * 4;
            float4 v = *(const float4*)(W + (size_t)(kt0 + kr) * CH + nt * 128 + nc);
            *(uint4*)&Bs[kr][nc] = make_uint4(f2t(v.x), f2t(v.y), f2t(v.z), f2t(v.w));
        }
        __syncthreads();
        #pragma unroll
        for (int ks = 0; ks < 4; ks++) {
            const int kk = ks * 8;
            unsigned a[2][4];
            #pragma unroll
            for (int mf = 0; mf < 2; mf++) {
                int r0 = wm + mf * 16 + g;
                a[mf][0] = As[r0    ][kk + tg];
                a[mf][1] = As[r0 + 8][kk + tg];
                a[mf][2] = As[r0    ][kk + tg + 4];
                a[mf][3] = As[r0 + 8][kk + tg + 4];
            }
            unsigned bf[8][2];
            #pragma unroll
            for (int nf = 0; nf < 8; nf++) {
                int c0 = wn + nf * 8 + g;
                bf[nf][0] = Bs[kk + tg    ][c0];
                bf[nf][1] = Bs[kk + tg + 4][c0];
            }
            #pragma unroll
            for (int mf = 0; mf < 2; mf++)
                #pragma unroll
                for (int nf = 0; nf < 8; nf++)
                    mma8(Creg[mf][nf], a[mf], bf[nf]);
        }
        __syncthreads();
    }
    #pragma unroll
    for (int mf = 0; mf < 2; mf++) {
        #pragma unroll
        for (int nf = 0; nf < 8; nf++) {
            int r = mt * 128 + wm + mf * 16 + g;
            int c = nt * 128 + wn + nf * 8 + tg * 2;
            float b0 = bias[c], b1 = bias[c + 1];
            out[(size_t)r * CH + c    ] = Creg[mf][nf][0] + b0;
            out[(size_t)r * CH + c + 1] = Creg[mf][nf][1] + b1;
            out[(size_t)(r + 8) * CH + c    ] = Creg[mf][nf][2] + b0;
            out[(size_t)(r + 8) * CH + c + 1] = Creg[mf][nf][3] + b1;
        }
    }
}

// =====================================================================
extern "C" void kernel_launch(void* const* d_in, const int* in_sizes, int n_in,
                              void* d_out, int out_size)
{
    const float* x     = (const float*)d_in[0];
    const float* sc    = (const float*)d_in[1];
    const float* Wqkv  = (const float*)d_in[2];
    const float* Wproj = (const float*)d_in[3];
    const float* bproj = (const float*)d_in[4];
    float* out = (float*)d_out;

    // QKV: M = 19520 -> 153 m-tiles, N = 2304 -> 18 n-tiles
    qkv_gemm<<<dim3(18, 153), 256>>>(x, sc, Wqkv);
    // attention: 16 q-tiles x 192 (b,h)
    attn_kernel<<<dim3(16, 192), 128>>>();
    // proj: M = 16384 -> 128 m-tiles, N = 768 -> 6 n-tiles
    proj_gemm<<<dim3(6, 128), 256>>>(Wproj, bproj, out);
}

// round 2
// speedup vs baseline: 1.0001x; 1.0001x over previous
#include <cuda_runtime.h>
#include <cstdint>

#define BATCH 16
#define SEQ   1024
#define CH    768
#define HEADS 12
#define DHEAD 64
#define NTOK  1220              // 1024 + 196
#define NKV   1280              // padded key count
#define MQKV  (BATCH*NTOK)      // 19520 rows of xt
#define QKVN  (3*CH)            // 2304

// ---------------- scratch (zero-initialized at module load; pad rows of K/V
// are never written so they stay 0.0 deterministically across graph replays) --
__device__ float g_Q [BATCH*HEADS*SEQ *DHEAD];   // [b][h][t<1024][d]
__device__ float g_K [BATCH*HEADS*NKV *DHEAD];   // [b][h][t<1280][d]
__device__ float g_V [BATCH*HEADS*NKV *DHEAD];
__device__ float g_AT[BATCH*SEQ*CH];             // attention out, [b*1024+t][h*64+d]

// ---------------- tf32 helpers ----------------
__device__ __forceinline__ unsigned f2t(float x){
    unsigned u; asm("cvt.rna.tf32.f32 %0, %1;" : "=r"(u) : "f"(x)); return u;
}
__device__ __forceinline__ void mma8(float* c, const unsigned* a, const unsigned* b){
    asm volatile("mma.sync.aligned.m16n8k8.row.col.f32.tf32.tf32.f32 "
        "{%0,%1,%2,%3}, {%4,%5,%6,%7}, {%8,%9}, {%0,%1,%2,%3};"
        : "+f"(c[0]), "+f"(c[1]), "+f"(c[2]), "+f"(c[3])
        : "r"(a[0]), "r"(a[1]), "r"(a[2]), "r"(a[3]), "r"(b[0]), "r"(b[1]));
}

// =====================================================================
// Kernel 1: QKV GEMM.  xt[19520,768] @ W_qkv[768,2304], scatter into
// g_Q/g_K/g_V head-major layouts.  Block tile 128x128, k-tile 32,
// 8 warps (4 m x 2 n), warp tile 32x64.
// =====================================================================
__global__ __launch_bounds__(256) void qkv_gemm(
    const float* __restrict__ x, const float* __restrict__ sc,
    const float* __restrict__ W)
{
    __shared__ unsigned As[128][36];   // [m][k], pad 36 -> conflict-free frag loads
    __shared__ unsigned Bs[32][132];   // [k][n]

    const int mt = blockIdx.y, nt = blockIdx.x;
    const int tid = threadIdx.x;
    const int wid = tid >> 5, lane = tid & 31;
    const int g = lane >> 2, tg = lane & 3;
    const int wm = (wid & 3) * 32, wn = (wid >> 2) * 64;

    float Creg[2][8][4];
    #pragma unroll
    for (int i = 0; i < 2; i++)
        #pragma unroll
        for (int j = 0; j < 8; j++)
            #pragma unroll
            for (int e = 0; e < 4; e++) Creg[i][j][e] = 0.f;

    for (int kt = 0; kt < CH / 32; kt++) {
        const int kt0 = kt * 32;
        // ---- load A tile (with xt row mapping) ----
        #pragma unroll
        for (int i = 0; i < 4; i++) {
            int slot = tid + i * 256;
            int row = slot >> 3, kc = (slot & 7) * 4;
            int gr = mt * 128 + row;
            float4 v = make_float4(0.f, 0.f, 0.f, 0.f);
            if (gr < MQKV) {
                int b = gr / NTOK, t = gr - b * NTOK;
                const float* src = (t < SEQ) ? (x + (size_t)(b * SEQ + t) * CH)
                                             : (sc + (size_t)(t - SEQ) * CH);
                v = *(const float4*)(src + kt0 + kc);
            }
            *(uint4*)&As[row][kc] = make_uint4(f2t(v.x), f2t(v.y), f2t(v.z), f2t(v.w));
        }
        // ---- load B tile ----
        #pragma unroll
        for (int i = 0; i < 4; i++) {
            int slot = tid + i * 256;
            int kr = slot >> 5, nc = (slot & 31) * 4;
            float4 v = *(const float4*)(W + (size_t)(kt0 + kr) * QKVN + nt * 128 + nc);
            *(uint4*)&Bs[kr][nc] = make_uint4(f2t(v.x), f2t(v.y), f2t(v.z), f2t(v.w));
        }
        __syncthreads();
        // ---- compute ----
        #pragma unroll
        for (int ks = 0; ks < 4; ks++) {
            const int kk = ks * 8;
            unsigned a[2][4];
            #pragma unroll
            for (int mf = 0; mf < 2; mf++) {
                int r0 = wm + mf * 16 + g;
                a[mf][0] = As[r0    ][kk + tg];
                a[mf][1] = As[r0 + 8][kk + tg];
                a[mf][2] = As[r0    ][kk + tg + 4];
                a[mf][3] = As[r0 + 8][kk + tg + 4];
            }
            unsigned bf[8][2];
            #pragma unroll
            for (int nf = 0; nf < 8; nf++) {
                int c0 = wn + nf * 8 + g;
                bf[nf][0] = Bs[kk + tg    ][c0];
                bf[nf][1] = Bs[kk + tg + 4][c0];
            }
            #pragma unroll
            for (int mf = 0; mf < 2; mf++)
                #pragma unroll
                for (int nf = 0; nf < 8; nf++)
                    mma8(Creg[mf][nf], a[mf], bf[nf]);
        }
        __syncthreads();
    }
    // ---- epilogue: scatter into Q/K/V ----
    #pragma unroll
    for (int mf = 0; mf < 2; mf++) {
        #pragma unroll
        for (int nf = 0; nf < 8; nf++) {
            #pragma unroll
            for (int e = 0; e < 4; e++) {
                int r = mt * 128 + wm + mf * 16 + g + ((e >= 2) ? 8 : 0);
                int c = nt * 128 + wn + nf * 8 + tg * 2 + (e & 1);
                if (r >= MQKV) continue;
                int b = r / NTOK, t = r - b * NTOK;
                int which = c / CH, cc = c - which * CH;
                int h = cc >> 6, d = cc & 63;
                float v = Creg[mf][nf][e];
                if (which == 0) {
                    if (t < SEQ) g_Q[((size_t)(b * HEADS + h) * SEQ + t) * DHEAD + d] = v;
                } else if (which == 1) {
                    g_K[((size_t)(b * HEADS + h) * NKV + t) * DHEAD + d] = v;
                } else {
                    g_V[((size_t)(b * HEADS + h) * NKV + t) * DHEAD + d] = v;
                }
            }
        }
    }
}

// =====================================================================
// Kernel 2: flash attention.  grid = (16 q-tiles, 192 bh), 4 warps.
// Each block: 64 q rows; loop 20 kv tiles of 64 keys (mask j>=1220).
// Q frags held in registers; P routed through the K smem buffer.
// =====================================================================
__global__ __launch_bounds__(128) void attn_kernel()
{
    __shared__ unsigned Ks[64][72];   // K tile, then reused for P
    __shared__ unsigned Vs[64][72];

    const int bh = blockIdx.y, qt = blockIdx.x;
    const int b = bh / HEADS, h = bh - b * HEADS;
    const int tid = threadIdx.x;
    const int w = tid >> 5, lane = tid & 31;
    const int g = lane >> 2, tg = lane & 3;

    const float* Qp = g_Q + (size_t)bh * SEQ * DHEAD;
    const float* Kp = g_K + (size_t)bh * NKV * DHEAD;
    const float* Vp = g_V + (size_t)bh * NKV * DHEAD;
    const int q0 = qt * 64 + w * 16;

    // Q fragments (row-major A, k = d)
    unsigned aq[8][4];
    #pragma unroll
    for (int ks = 0; ks < 8; ks++) {
        aq[ks][0] = f2t(Qp[(size_t)(q0 + g    ) * DHEAD + ks * 8 + tg    ]);
        aq[ks][1] = f2t(Qp[(size_t)(q0 + g + 8) * DHEAD + ks * 8 + tg    ]);
        aq[ks][2] = f2t(Qp[(size_t)(q0 + g    ) * DHEAD + ks * 8 + tg + 4]);
        aq[ks][3] = f2t(Qp[(size_t)(q0 + g + 8) * DHEAD + ks * 8 + tg + 4]);
    }

    float O[8][4];
    #pragma unroll
    for (int i = 0; i < 8; i++)
        #pragma unroll
        for (int e = 0; e < 4; e++) O[i][e] = 0.f;
    float mrow[2] = { -1e30f, -1e30f };
    float lrow[2] = { 0.f, 0.f };

    for (int kt = 0; kt < NKV / 64; kt++) {
        const int j0 = kt * 64;
        // ---- load K,V tiles (pad rows are zero-init, never written) ----
        #pragma unroll
        for (int i = 0; i < 8; i++) {
            int slot = tid + i * 128;
            int row = slot >> 4, c4 = (slot & 15) * 4;
            float4 kv = *(const float4*)(Kp + (size_t)(j0 + row) * DHEAD + c4);
            *(uint4*)&Ks[row][c4] = make_uint4(f2t(kv.x), f2t(kv.y), f2t(kv.z), f2t(kv.w));
            float4 vv = *(const float4*)(Vp + (size_t)(j0 + row) * DHEAD + c4);
            *(uint4*)&Vs[row][c4] = make_uint4(f2t(vv.x), f2t(vv.y), f2t(vv.z), f2t(vv.w));
        }
        __syncthreads();

        // ---- scores S = Q @ K^T  (B[k=d][n=key] = Ks[key][d]) ----
        float S[8][4];
        #pragma unroll
        for (int i = 0; i < 8; i++)
            #pragma unroll
            for (int e = 0; e < 4; e++) S[i][e] = 0.f;
        #pragma unroll
        for (int nf = 0; nf < 8; nf++) {
            #pragma unroll
            for (int ks = 0; ks < 8; ks++) {
                unsigned bb[2];
                bb[0] = Ks[nf * 8 + g][ks * 8 + tg    ];
                bb[1] = Ks[nf * 8 + g][ks * 8 + tg + 4];
                mma8(S[nf], aq[ks], bb);
            }
        }
        __syncthreads();   // everyone done reading Ks before it becomes P

        // ---- scale + mask ----
        #pragma unroll
        for (int nf = 0; nf < 8; nf++) {
            #pragma unroll
            for (int e = 0; e < 4; e++) {
                float s = S[nf][e] * 0.125f;
                int j = j0 + nf * 8 + tg * 2 + (e & 1);
                if (j >= NTOK) s = -1e30f;
                S[nf][e] = s;
            }
        }
        // ---- online softmax (thread owns rows g and g+8 of the warp tile) ----
        #pragma unroll
        for (int r = 0; r < 2; r++) {
            float mx = -1e30f;
            #pragma unroll
            for (int nf = 0; nf < 8; nf++) {
                mx = fmaxf(mx, S[nf][2 * r]);
                mx = fmaxf(mx, S[nf][2 * r + 1]);
            }
            mx = fmaxf(mx, __shfl_xor_sync(0xffffffffu, mx, 1));
            mx = fmaxf(mx, __shfl_xor_sync(0xffffffffu, mx, 2));
            float mnew = fmaxf(mrow[r], mx);
            float alpha = __expf(mrow[r] - mnew);
            float sum = 0.f;
            #pragma unroll
            for (int nf = 0; nf < 8; nf++) {
                float p0 = __expf(S[nf][2 * r    ] - mnew);
                float p1 = __expf(S[nf][2 * r + 1] - mnew);
                S[nf][2 * r] = p0; S[nf][2 * r + 1] = p1;
                sum += p0 + p1;
            }
            sum += __shfl_xor_sync(0xffffffffu, sum, 1);
            sum += __shfl_xor_sync(0xffffffffu, sum, 2);
            lrow[r] = lrow[r] * alpha + sum;
            mrow[r] = mnew;
            #pragma unroll
            for (int nf = 0; nf < 8; nf++) {
                O[nf][2 * r] *= alpha; O[nf][2 * r + 1] *= alpha;
            }
        }
        // ---- store P into Ks (warp-private 16 rows) ----
        #pragma unroll
        for (int nf = 0; nf < 8; nf++) {
            Ks[w * 16 + g    ][nf * 8 + tg * 2    ] = f2t(S[nf][0]);
            Ks[w * 16 + g    ][nf * 8 + tg * 2 + 1] = f2t(S[nf][1]);
            Ks[w * 16 + g + 8][nf * 8 + tg * 2    ] = f2t(S[nf][2]);
            Ks[w * 16 + g + 8][nf * 8 + tg * 2 + 1] = f2t(S[nf][3]);
        }
        __syncwarp();
        // ---- O += P @ V   (A = P 16x64, B[k=key][n=d] = Vs[key][d]) ----
        #pragma unroll
        for (int ks = 0; ks < 8; ks++) {
            unsigned ap[4];
            ap[0] = Ks[w * 16 + g    ][ks * 8 + tg    ];
            ap[1] = Ks[w * 16 + g + 8][ks * 8 + tg    ];
            ap[2] = Ks[w * 16 + g    ][ks * 8 + tg + 4];
            ap[3] = Ks[w * 16 + g + 8][ks * 8 + tg + 4];
            #pragma unroll
            for (int nf = 0; nf < 8; nf++) {
                unsigned bb[2];
                bb[0] = Vs[ks * 8 + tg    ][nf * 8 + g];
                bb[1] = Vs[ks * 8 + tg + 4][nf * 8 + g];
                mma8(O[nf], ap, bb);
            }
        }
        __syncthreads();   // before next tile overwrites Ks/Vs
    }
    // ---- normalize and write to g_AT [b*1024+t][h*64+d] ----
    float inv0 = 1.f / lrow[0], inv1 = 1.f / lrow[1];
    int row0 = b * SEQ + qt * 64 + w * 16 + g;
    #pragma unroll
    for (int nf = 0; nf < 8; nf++) {
        int col = h * DHEAD + nf * 8 + tg * 2;
        g_AT[(size_t)row0 * CH + col    ] = O[nf][0] * inv0;
        g_AT[(size_t)row0 * CH + col + 1] = O[nf][1] * inv0;
        g_AT[(size_t)(row0 + 8) * CH + col    ] = O[nf][2] * inv1;
        g_AT[(size_t)(row0 + 8) * CH + col + 1] = O[nf][3] * inv1;
    }
}

// =====================================================================
// Kernel 3: proj GEMM + bias.  g_AT[16384,768] @ W_proj[768,768] + b.
// =====================================================================
__global__ __launch_bounds__(256) void proj_gemm(
    const float* __restrict__ W, const float* __restrict__ bias,
    float* __restrict__ out)
{
    __shared__ unsigned As[128][36];
    __shared__ unsigned Bs[32][132];

    const int mt = blockIdx.y, nt = blockIdx.x;
    const int tid = threadIdx.x;
    const int wid = tid >> 5, lane = tid & 31;
    const int g = lane >> 2, tg = lane & 3;
    const int wm = (wid & 3) * 32, wn = (wid >> 2) * 64;

    float Creg[2][8][4];
    #pragma unroll
    for (int i = 0; i < 2; i++)
        #pragma unroll
        for (int j = 0; j < 8; j++)
            #pragma unroll
            for (int e = 0; e < 4; e++) Creg[i][j][e] = 0.f;

    for (int kt = 0; kt < CH / 32; kt++) {
        const int kt0 = kt * 32;
        #pragma unroll
        for (int i = 0; i < 4; i++) {
            int slot = tid + i * 256;
            int row = slot >> 3, kc = (slot & 7) * 4;
            float4 v = *(const float4*)(g_AT + (size_t)(mt * 128 + row) * CH + kt0 + kc);
            *(uint4*)&As[row][kc] = make_uint4(f2t(v.x), f2t(v.y), f2t(v.z), f2t(v.w));
        }
        #pragma unroll
        for (int i = 0; i < 4; i++) {
            int slot = tid + i * 256;
            int kr = slot >> 5, nc = (slot & 31) * 4;
            float4 v = *(const float4*)(W + (size_t)(kt0 + kr) * CH + nt * 128 + nc);
            *(uint4*)&Bs[kr][nc] = make_uint4(f2t(v.x), f2t(v.y), f2t(v.z), f2t(v.w));
        }
        __syncthreads();
        #pragma unroll
        for (int ks = 0; ks < 4; ks++) {
            const int kk = ks * 8;
            unsigned a[2][4];
            #pragma unroll
            for (int mf = 0; mf < 2; mf++) {
                int r0 = wm + mf * 16 + g;
                a[mf][0] = As[r0    ][kk + tg];
                a[mf][1] = As[r0 + 8][kk + tg];
                a[mf][2] = As[r0    ][kk + tg + 4];
                a[mf][3] = As[r0 + 8][kk + tg + 4];
            }
            unsigned bf[8][2];
            #pragma unroll
            for (int nf = 0; nf < 8; nf++) {
                int c0 = wn + nf * 8 + g;
                bf[nf][0] = Bs[kk + tg    ][c0];
                bf[nf][1] = Bs[kk + tg + 4][c0];
            }
            #pragma unroll
            for (int mf = 0; mf < 2; mf++)
                #pragma unroll
                for (int nf = 0; nf < 8; nf++)
                    mma8(Creg[mf][nf], a[mf], bf[nf]);
        }
        __syncthreads();
    }
    #pragma unroll
    for (int mf = 0; mf < 2; mf++) {
        #pragma unroll
        for (int nf = 0; nf < 8; nf++) {
            int r = mt * 128 + wm + mf * 16 + g;
            int c = nt * 128 + wn + nf * 8 + tg * 2;
            float b0 = bias[c], b1 = bias[c + 1];
            out[(size_t)r * CH + c    ] = Creg[mf][nf][0] + b0;
            out[(size_t)r * CH + c + 1] = Creg[mf][nf][1] + b1;
            out[(size_t)(r + 8) * CH + c    ] = Creg[mf][nf][2] + b0;
            out[(size_t)(r + 8) * CH + c + 1] = Creg[mf][nf][3] + b1;
        }
    }
}

// =====================================================================
extern "C" void kernel_launch(void* const* d_in, const int* in_sizes, int n_in,
                              void* d_out, int out_size)
{
    const float* x     = (const float*)d_in[0];
    const float* sc    = (const float*)d_in[1];
    const float* Wqkv  = (const float*)d_in[2];
    const float* Wproj = (const float*)d_in[3];
    const float* bproj = (const float*)d_in[4];
    float* out = (float*)d_out;

    // QKV: M = 19520 -> 153 m-tiles, N = 2304 -> 18 n-tiles
    qkv_gemm<<<dim3(18, 153), 256>>>(x, sc, Wqkv);
    // attention: 16 q-tiles x 192 (b,h)
    attn_kernel<<<dim3(16, 192), 128>>>();
    // proj: M = 16384 -> 128 m-tiles, N = 768 -> 6 n-tiles
    proj_gemm<<<dim3(6, 128), 256>>>(Wproj, bproj, out);
}